// round 12
// baseline (speedup 1.0000x reference)
#include <cuda_runtime.h>
#include <float.h>

// ROI max pooling, exact integer-bin partition (matches reference):
//   cell (py,px) of roi (y0,x0,h,w) covers rows [y0 + py*h/7, y0 + (py+1)*h/7)
//   and cols [x0 + px*w/7, x0 + (px+1)*w/7). h,w >= 7 so cells are non-empty.
//
// Shapes: feature_map [B=2, H=38, W=38, C=512] f32, rois [B=2, N=64, 4] i32,
// out [B, N, 7, 7, C] f32.
//
// R10 -> R11: falsified: MLP (R9), occ-via-bundling (R10), smem split (R8);
// magic-div decode costs ~0.5us of ALU in the load path (R9/R10). This round:
// unit = (cell, channel-QUARTER) (25088 units, 1 float4/thread, ~40 regs),
// 2-warp blocks pairing two quarters of the SAME cell (identical durations ->
// no CTA-retire coupling waste; removes the 32-block/SM warp cap), explicit
// y2x2 pointer-stride unroll, no smem/sync.

#define H_DIM 38
#define W_DIM 38
#define C4 128           // C/4 float4 groups per pixel
#define POOL 7
#define ROWSTRIDE (W_DIM * C4)

__device__ __forceinline__ void fmax4(float4& m, const float4 v) {
    m.x = fmaxf(m.x, v.x);
    m.y = fmaxf(m.y, v.y);
    m.z = fmaxf(m.z, v.z);
    m.w = fmaxf(m.w, v.w);
}

__global__ __launch_bounds__(64) void roi_pool_kernel(
    const float4* __restrict__ fm,   // [B, H, W, C/4] as float4
    const int*    __restrict__ rois, // [B*N, 4] (y, x, h, w)
    float4*       __restrict__ out,  // [B*N, 49, C/4] as float4
    int n_per_b)                     // N (rois per batch)
{
    const int cell = blockIdx.x;        // roi*49 + py*7 + px
    const int px   = cell % POOL;
    const int py   = (cell / POOL) % POOL;
    const int roi  = cell / (POOL * POOL);
    const int b    = roi / n_per_b;

    const int4 r = __ldg((const int4*)(rois + roi * 4));
    const int y0 = r.x, x0 = r.y, h = r.z, w = r.w;

    const int ys = y0 + (py * h) / POOL;
    const int ye = y0 + ((py + 1) * h) / POOL;
    const int xs = x0 + (px * w) / POOL;
    const int xe = x0 + ((px + 1) * w) / POOL;

    // quarter = blockIdx.y*2 + warp; thread owns float4 slot quarter*32+lane.
    // Both warps of a block are quarters of the SAME cell: identical work.
    const int lane = threadIdx.x & 31;
    const int c = ((blockIdx.y << 1) + (threadIdx.x >> 5)) * 32 + lane;
    const float4* base = fm + ((size_t)b * H_DIM * W_DIM) * C4 + c;

    float4 m = make_float4(-FLT_MAX, -FLT_MAX, -FLT_MAX, -FLT_MAX);

    int y = ys;
    // ---- y-unroll 2, x-unroll 2: 4 independent LDG.128 per iteration ----
    for (; y + 1 < ye; y += 2) {
        const float4* p0 = base + ((size_t)(y * W_DIM + xs)) * C4;
        const float4* p1 = p0 + ROWSTRIDE;
        int x = xs;
        for (; x + 1 < xe; x += 2, p0 += 2 * C4, p1 += 2 * C4) {
            float4 a0 = __ldg(p0);
            float4 a1 = __ldg(p0 + C4);
            float4 b0 = __ldg(p1);
            float4 b1 = __ldg(p1 + C4);
            fmax4(m, a0); fmax4(m, a1);
            fmax4(m, b0); fmax4(m, b1);
        }
        if (x < xe) {
            float4 a0 = __ldg(p0);
            float4 b0 = __ldg(p1);
            fmax4(m, a0); fmax4(m, b0);
        }
    }
    // ---- remainder row (odd cell height), x-unroll 2 ----
    if (y < ye) {
        const float4* p0 = base + ((size_t)(y * W_DIM + xs)) * C4;
        int x = xs;
        for (; x + 1 < xe; x += 2, p0 += 2 * C4) {
            float4 a0 = __ldg(p0);
            float4 a1 = __ldg(p0 + C4);
            fmax4(m, a0); fmax4(m, a1);
        }
        if (x < xe) {
            float4 a0 = __ldg(p0);
            fmax4(m, a0);
        }
    }

    out[(size_t)cell * C4 + c] = m;
}

extern "C" void kernel_launch(void* const* d_in, const int* in_sizes, int n_in,
                              void* d_out, int out_size) {
    const float4* fm   = (const float4*)d_in[0];
    const int*    rois = (const int*)d_in[1];
    float4*       out  = (float4*)d_out;

    const int n_rois  = in_sizes[1] / 4;     // B*N = 128
    const int B       = 2;                   // fixed per problem shapes
    const int n_per_b = n_rois / B;          // N = 64

    dim3 grid(n_rois * POOL * POOL, 2);      // 6272 cells x 2 quarter-pairs
    roi_pool_kernel<<<grid, 64>>>(fm, rois, out, n_per_b);
}

// round 13
// speedup vs baseline: 1.0106x; 1.0106x over previous
#include <cuda_runtime.h>
#include <float.h>

// ROI max pooling, exact integer-bin partition (matches reference):
//   cell (py,px) of roi (y0,x0,h,w) covers rows [y0 + py*h/7, y0 + (py+1)*h/7)
//   and cols [x0 + px*w/7, x0 + (px+1)*w/7). h,w >= 7 so cells are non-empty.
//
// Shapes: feature_map [B=2, H=38, W=38, C=512] f32, rois [B=2, N=64, 4] i32,
// out [B, N, 7, 7, C] f32.
//
// R11 -> R12: evidence across R1/R3/R4/R11: fatter warps win, occupancy is
// irrelevant (R11: occ 74%, 16.7us; R4: occ 31%, 12.0us). Per-warp serial
// prologue (roi load -> bounds -> first batch) and loop overhead scale with
// warp count. So: ONE warp per cell, full 512 channels (4 float4/thread),
// 6272 warp-lifetimes (half of R4). x-unroll-2 keeps 8 LDG.128 in flight
// (R4-proven ILP) at ~72 regs. 32-thr blocks, no smem, no sync.

#define H_DIM 38
#define W_DIM 38
#define C4 128           // C/4 float4 groups per pixel
#define POOL 7

__device__ __forceinline__ void fmax4(float4& m, const float4 v) {
    m.x = fmaxf(m.x, v.x);
    m.y = fmaxf(m.y, v.y);
    m.z = fmaxf(m.z, v.z);
    m.w = fmaxf(m.w, v.w);
}

__global__ __launch_bounds__(32) void roi_pool_kernel(
    const float4* __restrict__ fm,   // [B, H, W, C/4] as float4
    const int*    __restrict__ rois, // [B*N, 4] (y, x, h, w)
    float4*       __restrict__ out,  // [B*N, 49, C/4] as float4
    int n_per_b)                     // N (rois per batch)
{
    const int cell = blockIdx.x;        // roi*49 + py*7 + px
    const int px   = cell % POOL;
    const int py   = (cell / POOL) % POOL;
    const int roi  = cell / (POOL * POOL);
    const int b    = roi / n_per_b;

    const int4 r = __ldg((const int4*)(rois + roi * 4));
    const int y0 = r.x, x0 = r.y, h = r.z, w = r.w;

    const int ys = y0 + (py * h) / POOL;
    const int ye = y0 + ((py + 1) * h) / POOL;
    const int xs = x0 + (px * w) / POOL;
    const int xe = x0 + ((px + 1) * w) / POOL;

    const int lane = threadIdx.x;       // owns slots lane, +32, +64, +96
    const float4* base = fm + ((size_t)b * H_DIM * W_DIM) * C4 + lane;

    float4 m0 = make_float4(-FLT_MAX, -FLT_MAX, -FLT_MAX, -FLT_MAX);
    float4 m1 = m0, m2 = m0, m3 = m0;

    for (int y = ys; y < ye; ++y) {
        const float4* p = base + ((size_t)(y * W_DIM + xs)) * C4;
        int x = xs;
        // x-unroll 2: 8 independent LDG.128 in flight
        for (; x + 1 < xe; x += 2, p += 2 * C4) {
            float4 a0 = __ldg(p);
            float4 a1 = __ldg(p + 32);
            float4 a2 = __ldg(p + 64);
            float4 a3 = __ldg(p + 96);
            float4 b0 = __ldg(p + C4);
            float4 b1 = __ldg(p + C4 + 32);
            float4 b2 = __ldg(p + C4 + 64);
            float4 b3 = __ldg(p + C4 + 96);
            fmax4(m0, a0); fmax4(m1, a1); fmax4(m2, a2); fmax4(m3, a3);
            fmax4(m0, b0); fmax4(m1, b1); fmax4(m2, b2); fmax4(m3, b3);
        }
        if (x < xe) {
            float4 a0 = __ldg(p);
            float4 a1 = __ldg(p + 32);
            float4 a2 = __ldg(p + 64);
            float4 a3 = __ldg(p + 96);
            fmax4(m0, a0); fmax4(m1, a1); fmax4(m2, a2); fmax4(m3, a3);
        }
    }

    float4* o = out + (size_t)cell * C4 + lane;
    o[0]  = m0;
    o[32] = m1;
    o[64] = m2;
    o[96] = m3;
}

extern "C" void kernel_launch(void* const* d_in, const int* in_sizes, int n_in,
                              void* d_out, int out_size) {
    const float4* fm   = (const float4*)d_in[0];
    const int*    rois = (const int*)d_in[1];
    float4*       out  = (float4*)d_out;

    const int n_rois  = in_sizes[1] / 4;     // B*N = 128
    const int B       = 2;                   // fixed per problem shapes
    const int n_per_b = n_rois / B;          // N = 64

    const int grid = n_rois * POOL * POOL;   // 6272 cells, 1 warp each
    roi_pool_kernel<<<grid, 32>>>(fm, rois, out, n_per_b);
}